// round 12
// baseline (speedup 1.0000x reference)
#include <cuda_runtime.h>
#include <cuda_fp16.h>
#include <cstdint>
#include <math.h>

#define TT   512
#define HD   2048
#define EE   32
#define KTOP 4
#define FF   1024
#define NZ   16
#define ZHD  512

__device__ float  g_zh[TT * ZHD];
__device__ __half g_xh[TT * HD];
__device__ __half g_acth[(size_t)EE * TT * FF];
__device__ int    g_cnt[EE];
__device__ int    g_tok[EE * TT];
__device__ float  g_wgt[EE * TT];

__device__ __forceinline__ unsigned f2tf(float f) {
    unsigned u;
    asm("cvt.rna.tf32.f32 %0, %1;" : "=r"(u) : "f"(f));
    return u;
}
__device__ __forceinline__ unsigned pack_h2(float lo, float hi) {
    unsigned d;
    asm("cvt.rn.f16x2.f32 %0, %1, %2;" : "=r"(d) : "f"(hi), "f"(lo));
    return d;
}
__device__ __forceinline__ uint32_t smem_u32(const void* p) {
    uint32_t a;
    asm("{ .reg .u64 t; cvta.to.shared.u64 t, %1; cvt.u32.u64 %0, t; }" : "=r"(a) : "l"(p));
    return a;
}
__device__ __forceinline__ void cp16(uint32_t dst, const void* src) {
    asm volatile("cp.async.cg.shared.global [%0], [%1], 16;" :: "r"(dst), "l"(src));
}
#define CP_COMMIT() asm volatile("cp.async.commit_group;" ::: "memory")
#define CP_WAIT3()  asm volatile("cp.async.wait_group 3;" ::: "memory")
#define CP_WAIT4()  asm volatile("cp.async.wait_group 4;" ::: "memory")

__device__ __forceinline__ void mma_tf32(float& d0, float& d1, float& d2, float& d3,
                                         unsigned a0, unsigned a1, unsigned a2, unsigned a3,
                                         unsigned b0, unsigned b1) {
    asm volatile("mma.sync.aligned.m16n8k8.row.col.f32.tf32.tf32.f32 "
                 "{%0,%1,%2,%3}, {%4,%5,%6,%7}, {%8,%9}, {%0,%1,%2,%3};"
                 : "+f"(d0), "+f"(d1), "+f"(d2), "+f"(d3)
                 : "r"(a0), "r"(a1), "r"(a2), "r"(a3), "r"(b0), "r"(b1));
}
__device__ __forceinline__ void mma_f16(float& d0, float& d1, float& d2, float& d3,
                                        unsigned a0, unsigned a1, unsigned a2, unsigned a3,
                                        unsigned b0, unsigned b1) {
    asm volatile("mma.sync.aligned.m16n8k16.row.col.f32.f16.f16.f32 "
                 "{%0,%1,%2,%3}, {%4,%5,%6,%7}, {%8,%9}, {%0,%1,%2,%3};"
                 : "+f"(d0), "+f"(d1), "+f"(d2), "+f"(d3)
                 : "r"(a0), "r"(a1), "r"(a2), "r"(a3), "r"(b0), "r"(b1));
}

// ---------------------------------------------------------------------------
// K0: zero output + counters + fp16 copy of x
// ---------------------------------------------------------------------------
__global__ void k_zero(float* __restrict__ out, const float* __restrict__ x) {
    int i = blockIdx.x * blockDim.x + threadIdx.x;
    if (i < TT * HD) {
        out[i] = 0.0f;
        g_xh[i] = __float2half_rn(x[i]);
    }
    if (i < EE) g_cnt[i] = 0;
}

// ---------------------------------------------------------------------------
// K1: zh = silu(x @ z_w1^T + b1). tf32 (small; unchanged)
// ---------------------------------------------------------------------------
__global__ __launch_bounds__(256, 2) void k_zh(const float* __restrict__ x,
                                               const float* __restrict__ w1,
                                               const float* __restrict__ b1) {
    int m0 = blockIdx.y * 128, n0 = blockIdx.x * 64;
    __shared__ unsigned As[128][20];
    __shared__ unsigned Bs[64][20];
    int tid = threadIdx.x, lane = tid & 31, warp = tid >> 5;
    int wm = warp >> 1, wn = warp & 1;
    int lq = lane >> 2, lr = lane & 3;
    int bn = tid >> 2, bkc = (tid & 3) * 4;

    float acc[2][4][4] = {};
    float4 rA[2], rB;
#pragma unroll
    for (int p = 0; p < 2; p++) {
        int s = tid + p * 256, r = s >> 2, kc = (s & 3) * 4;
        rA[p] = *(const float4*)&x[(size_t)(m0 + r) * HD + kc];
    }
    rB = *(const float4*)&w1[(size_t)(n0 + bn) * HD + bkc];
#pragma unroll
    for (int p = 0; p < 2; p++) {
        int s = tid + p * 256, r = s >> 2, kc = (s & 3) * 4;
        uint4 w = {f2tf(rA[p].x), f2tf(rA[p].y), f2tf(rA[p].z), f2tf(rA[p].w)};
        *(uint4*)&As[r][kc] = w;
    }
    {
        uint4 w = {f2tf(rB.x), f2tf(rB.y), f2tf(rB.z), f2tf(rB.w)};
        *(uint4*)&Bs[bn][bkc] = w;
    }
    __syncthreads();

    for (int k0 = 0; k0 < HD; k0 += 16) {
        bool more = (k0 + 16) < HD;
        if (more) {
            int kn = k0 + 16;
#pragma unroll
            for (int p = 0; p < 2; p++) {
                int s = tid + p * 256, r = s >> 2, kc = (s & 3) * 4;
                rA[p] = *(const float4*)&x[(size_t)(m0 + r) * HD + kn + kc];
            }
            rB = *(const float4*)&w1[(size_t)(n0 + bn) * HD + kn + bkc];
        }
#pragma unroll
        for (int k8 = 0; k8 < 2; k8++) {
            int kb = k8 * 8 + lr;
            unsigned a[2][4];
#pragma unroll
            for (int mi = 0; mi < 2; mi++) {
                int r = wm * 32 + mi * 16 + lq;
                a[mi][0] = As[r][kb];     a[mi][1] = As[r + 8][kb];
                a[mi][2] = As[r][kb + 4]; a[mi][3] = As[r + 8][kb + 4];
            }
#pragma unroll
            for (int ni = 0; ni < 4; ni++) {
                int nn = wn * 32 + ni * 8 + lq;
                unsigned b0 = Bs[nn][kb], b1r = Bs[nn][kb + 4];
#pragma unroll
                for (int mi = 0; mi < 2; mi++)
                    mma_tf32(acc[mi][ni][0], acc[mi][ni][1], acc[mi][ni][2], acc[mi][ni][3],
                             a[mi][0], a[mi][1], a[mi][2], a[mi][3], b0, b1r);
            }
        }
        __syncthreads();
        if (more) {
#pragma unroll
            for (int p = 0; p < 2; p++) {
                int s = tid + p * 256, r = s >> 2, kc = (s & 3) * 4;
                uint4 w = {f2tf(rA[p].x), f2tf(rA[p].y), f2tf(rA[p].z), f2tf(rA[p].w)};
                *(uint4*)&As[r][kc] = w;
            }
            uint4 w = {f2tf(rB.x), f2tf(rB.y), f2tf(rB.z), f2tf(rB.w)};
            *(uint4*)&Bs[bn][bkc] = w;
            __syncthreads();
        }
    }
#pragma unroll
    for (int mi = 0; mi < 2; mi++)
#pragma unroll
        for (int half = 0; half < 2; half++) {
            int r = m0 + wm * 32 + mi * 16 + lq + half * 8;
#pragma unroll
            for (int ni = 0; ni < 4; ni++)
#pragma unroll
                for (int c = 0; c < 2; c++) {
                    int col = n0 + wn * 32 + ni * 8 + lr * 2 + c;
                    float v = acc[mi][ni][half * 2 + c] + b1[col];
                    g_zh[(size_t)r * ZHD + col] = v / (1.0f + expf(-v));
                }
        }
}

// ---------------------------------------------------------------------------
// K2: per-token router (unchanged)
// ---------------------------------------------------------------------------
__global__ __launch_bounds__(128) void k_router(const float* __restrict__ x,
                                                const float* __restrict__ u,
                                                const float* __restrict__ gate_w,
                                                const float* __restrict__ z_w2,
                                                const float* __restrict__ z_b2,
                                                const float* __restrict__ Umat) {
    int t = blockIdx.x;
    __shared__ float xs[HD];
    __shared__ float rl[EE];
    __shared__ float zl[NZ];
    int tid = threadIdx.x, lane = tid & 31, warp = tid >> 5;

    for (int i = tid; i < HD; i += 128) xs[i] = x[t * HD + i];
    __syncthreads();

    for (int e = warp; e < EE; e += 4) {
        float s = 0.0f;
        const float* gw = gate_w + e * HD;
        for (int i = lane; i < HD; i += 32) s += xs[i] * gw[i];
#pragma unroll
        for (int o = 16; o; o >>= 1) s += __shfl_down_sync(0xffffffffu, s, o);
        if (lane == 0) rl[e] = s;
    }
    for (int j = warp; j < NZ; j += 4) {
        float s = 0.0f;
        const float* zw = z_w2 + j * ZHD;
        const float* zh = g_zh + t * ZHD;
        for (int i = lane; i < ZHD; i += 32) s += zh[i] * zw[i];
#pragma unroll
        for (int o = 16; o; o >>= 1) s += __shfl_down_sync(0xffffffffu, s, o);
        if (lane == 0) zl[j] = s + z_b2[j];
    }
    __syncthreads();

    if (tid == 0) {
        int zi = 0;
        float best = -1e30f;
        for (int j = 0; j < NZ; j++) {
            float g = -logf(-logf(u[t * NZ + j]));
            float v = zl[j] + g;
            if (v > best) { best = v; zi = j; }
        }
        float lg[EE];
        float mx = -1e30f;
        for (int e = 0; e < EE; e++) {
            lg[e] = rl[e] + Umat[zi * EE + e];
            mx = fmaxf(mx, lg[e]);
        }
        float sum = 0.0f;
        for (int e = 0; e < EE; e++) { lg[e] = expf(lg[e] - mx); sum += lg[e]; }
        float inv = 1.0f / sum;
        for (int k = 0; k < KTOP; k++) {
            int be = 0;
            float bv = -1.0f;
            for (int e = 0; e < EE; e++)
                if (lg[e] > bv) { bv = lg[e]; be = e; }
            float w = bv * inv;
            lg[be] = -1.0f;
            int pos = atomicAdd(&g_cnt[be], 1);
            g_tok[be * TT + pos] = t;
            g_wgt[be * TT + pos] = w;
        }
    }
}

// ---------------------------------------------------------------------------
// K3: gate/up, warp-split matrices, 5-stage cp.async, fp16 mma, 3 CTAs/SM.
// CTA: M=128 tokens x 32 f-cols of BOTH Wg and Wu. grid (FF/32, EE) = 1024.
// Warps 0-3: gate (wm = warp, m32 x n32); warps 4-7: up.
// Stage (10752 B) @1024+s*10752:
//   A fp16 [128][12w] (6144) | Bg f32 [16][36w] (2304) | Bu f32 [16][36w] (2304)
// C exchange buffer (overlaps stages, used after k-loop):
//   Cg [128][36] f32 @1024, Cu @1024+18432  (36864 B total)
// ---------------------------------------------------------------------------
#define GU_ST    10752
#define GU_SMEM  (1024 + 5 * GU_ST)

__global__ __launch_bounds__(256, 3) void k_gateup(const float* __restrict__ Wg,
                                                   const float* __restrict__ Wu) {
    extern __shared__ char smem[];
    int e = blockIdx.y;
    int n = g_cnt[e];
    if (n == 0) return;
    int f0 = blockIdx.x * 32;
    uint32_t sb = smem_u32(smem);
    int tid = threadIdx.x, lane = tid & 31, warp = tid >> 5;
    int wmat = warp >> 2;          // 0 = gate, 1 = up
    int wm = warp & 3;             // m32 block
    int lq = lane >> 2, lr = lane & 3;
    int* toks = (int*)smem;
    const float* wg = Wg + (size_t)e * HD * FF + f0;
    const float* wu = Wu + (size_t)e * HD * FF + f0;

    int ar = tid >> 1, ac = tid & 1;                 // A staging
    int bkk = (tid & 127) >> 3, bcc = tid & 7;       // B staging
    const float* wsel = (tid < 128) ? wg : wu;
    uint32_t boff = 6144 + (tid < 128 ? 0 : 2304) + (uint32_t)bkk * 144 + (uint32_t)bcc * 16;

    for (int s0 = 0; s0 < n; s0 += 128) {
        __syncthreads();
        int nt = min(128, n - s0);
        if (tid < 128) toks[tid] = g_tok[e * TT + s0 + ((tid < nt) ? tid : 0)];
        __syncthreads();
        const __half* xrow = g_xh + (size_t)toks[ar] * HD;

        // prologue: stages 0..3
#pragma unroll
        for (int s = 0; s < 4; s++) {
            uint32_t st = sb + 1024 + s * GU_ST;
            cp16(st + ar * 48 + ac * 16, xrow + s * 16 + ac * 8);
            cp16(st + boff, wsel + (size_t)(s * 16 + bkk) * FF + bcc * 4);
            CP_COMMIT();
        }

        float acc[2][4][4] = {};

        int cur = 0;
        for (int i = 0; i < 128; i++) {
            CP_WAIT3();
            __syncthreads();
            int nx = i + 4;
            if (nx < 128) {
                int nst = nx % 5;
                uint32_t st = sb + 1024 + nst * GU_ST;
                int kn = nx * 16;
                cp16(st + ar * 48 + ac * 16, xrow + kn + ac * 8);
                cp16(st + boff, wsel + (size_t)(kn + bkk) * FF + bcc * 4);
            }
            CP_COMMIT();

            const char* stg = smem + 1024 + cur * GU_ST;
            const unsigned* Aw = (const unsigned*)stg;
            const float* B = (const float*)(stg + 6144 + wmat * 2304);

            unsigned a[2][4];
#pragma unroll
            for (int mi = 0; mi < 2; mi++) {
                int r = wm * 32 + mi * 16 + lq;
                a[mi][0] = Aw[r * 12 + lr];
                a[mi][1] = Aw[(r + 8) * 12 + lr];
                a[mi][2] = Aw[r * 12 + lr + 4];
                a[mi][3] = Aw[(r + 8) * 12 + lr + 4];
            }
#pragma unroll
            for (int ni = 0; ni < 4; ni++) {
                int nn = ni * 8 + lq;
                unsigned b0 = pack_h2(B[(2 * lr) * 36 + nn],     B[(2 * lr + 1) * 36 + nn]);
                unsigned b1 = pack_h2(B[(2 * lr + 8) * 36 + nn], B[(2 * lr + 9) * 36 + nn]);
#pragma unroll
                for (int mi = 0; mi < 2; mi++)
                    mma_f16(acc[mi][ni][0], acc[mi][ni][1], acc[mi][ni][2], acc[mi][ni][3],
                            a[mi][0], a[mi][1], a[mi][2], a[mi][3], b0, b1);
            }
            if (++cur == 5) cur = 0;
        }

        // exchange: acc -> C buffer (overlaps stage area; all stage reads done)
        __syncthreads();
        {
            float* C = (float*)(smem + 1024) + wmat * (128 * 36);
#pragma unroll
            for (int mi = 0; mi < 2; mi++)
#pragma unroll
                for (int half = 0; half < 2; half++) {
                    int r = wm * 32 + mi * 16 + lq + half * 8;
#pragma unroll
                    for (int ni = 0; ni < 4; ni++) {
                        float2 v = make_float2(acc[mi][ni][half * 2],
                                               acc[mi][ni][half * 2 + 1]);
                        *(float2*)&C[r * 36 + ni * 8 + lr * 2] = v;
                    }
                }
        }
        __syncthreads();

        // combine: SwiGLU * comb -> g_acth (each thread: one row-half)
        {
            int rr = tid >> 1, cb = (tid & 1) * 16;
            if (rr < nt) {
                float wc = g_wgt[e * TT + s0 + rr];
                const float* Cg = (const float*)(smem + 1024);
                const float* Cu = Cg + 128 * 36;
                size_t base = ((size_t)e * TT + s0 + rr) * FF + f0 + cb;
#pragma unroll
                for (int j = 0; j < 16; j += 2) {
                    float g0 = Cg[rr * 36 + cb + j],     u0 = Cu[rr * 36 + cb + j];
                    float g1 = Cg[rr * 36 + cb + j + 1], u1 = Cu[rr * 36 + cb + j + 1];
                    float a0 = g0 / (1.0f + expf(-g0)) * u0 * wc;
                    float a1 = g1 / (1.0f + expf(-g1)) * u1 * wc;
                    *(unsigned*)&g_acth[base + j] = pack_h2(a0, a1);
                }
            }
        }
        __syncthreads();
    }
}

// ---------------------------------------------------------------------------
// K4: down projection, 6-stage cp.async pipeline, fp16 mma, 3 CTAs/SM.
// M=128 x N=64, K=FF. grid (HD/64, EE).
// Stage (10496 B): A fp16 [128][12w] (6144 B) | B f32 [16][68w] (4352 B)
// ---------------------------------------------------------------------------
#define DN_ST    10496
#define DN_SMEM  (1024 + 6 * DN_ST)

__global__ __launch_bounds__(256, 3) void k_down(const float* __restrict__ Wd,
                                                 float* __restrict__ out) {
    extern __shared__ char smem[];
    int e = blockIdx.y;
    int n = g_cnt[e];
    if (n == 0) return;
    int h0 = blockIdx.x * 64;
    uint32_t sb = smem_u32(smem);
    int tid = threadIdx.x, lane = tid & 31, warp = tid >> 5;
    int wm = warp >> 1, wn = warp & 1;
    int lq = lane >> 2, lr = lane & 3;
    int* toks = (int*)smem;
    const float* wd = Wd + (size_t)e * FF * HD + h0;

    int ar = tid >> 1, ac = tid & 1;
    int bkk = tid >> 4, bcc = tid & 15;

    for (int s0 = 0; s0 < n; s0 += 128) {
        __syncthreads();
        int nt = min(128, n - s0);
        if (tid < 128) toks[tid] = g_tok[e * TT + s0 + ((tid < nt) ? tid : 0)];
        __syncthreads();

        const __half* arow = g_acth + ((size_t)e * TT + s0 + ((ar < nt) ? ar : 0)) * FF;

#pragma unroll
        for (int s = 0; s < 5; s++) {
            uint32_t st = sb + 1024 + s * DN_ST;
            cp16(st + ar * 48 + ac * 16, arow + s * 16 + ac * 8);
            cp16(st + 6144 + bkk * 272 + bcc * 16, wd + (size_t)(s * 16 + bkk) * HD + bcc * 4);
            CP_COMMIT();
        }

        float acc[2][4][4] = {};

        int cur = 0;
        for (int i = 0; i < 64; i++) {
            CP_WAIT4();
            __syncthreads();
            int nx = i + 5;
            if (nx < 64) {
                int nst = nx % 6;
                uint32_t st = sb + 1024 + nst * DN_ST;
                int kn = nx * 16;
                cp16(st + ar * 48 + ac * 16, arow + kn + ac * 8);
                cp16(st + 6144 + bkk * 272 + bcc * 16, wd + (size_t)(kn + bkk) * HD + bcc * 4);
            }
            CP_COMMIT();

            const char* stg = smem + 1024 + cur * DN_ST;
            const unsigned* Aw = (const unsigned*)stg;
            const float* B = (const float*)(stg + 6144);

            unsigned a[2][4];
#pragma unroll
            for (int mi = 0; mi < 2; mi++) {
                int r = wm * 32 + mi * 16 + lq;
                a[mi][0] = Aw[r * 12 + lr];
                a[mi][1] = Aw[(r + 8) * 12 + lr];
                a[mi][2] = Aw[r * 12 + lr + 4];
                a[mi][3] = Aw[(r + 8) * 12 + lr + 4];
            }
#pragma unroll
            for (int ni = 0; ni < 4; ni++) {
                int nn = wn * 32 + ni * 8 + lq;
                unsigned b0 = pack_h2(B[(2 * lr) * 68 + nn],     B[(2 * lr + 1) * 68 + nn]);
                unsigned b1 = pack_h2(B[(2 * lr + 8) * 68 + nn], B[(2 * lr + 9) * 68 + nn]);
#pragma unroll
                for (int mi = 0; mi < 2; mi++)
                    mma_f16(acc[mi][ni][0], acc[mi][ni][1], acc[mi][ni][2], acc[mi][ni][3],
                            a[mi][0], a[mi][1], a[mi][2], a[mi][3], b0, b1);
            }
            if (++cur == 6) cur = 0;
        }

        // epilogue: atomicAdd into out
#pragma unroll
        for (int mi = 0; mi < 2; mi++)
#pragma unroll
            for (int half = 0; half < 2; half++) {
                int r = wm * 32 + mi * 16 + lq + half * 8;
                if (r < nt) {
                    int t = toks[r];
                    size_t base = (size_t)t * HD + h0 + wn * 32;
#pragma unroll
                    for (int ni = 0; ni < 4; ni++)
#pragma unroll
                        for (int c = 0; c < 2; c++)
                            atomicAdd(&out[base + ni * 8 + lr * 2 + c],
                                      acc[mi][ni][half * 2 + c]);
                }
            }
    }
}

// ---------------------------------------------------------------------------
// launch
// ---------------------------------------------------------------------------
extern "C" void kernel_launch(void* const* d_in, const int* in_sizes, int n_in,
                              void* d_out, int out_size) {
    const float* x      = (const float*)d_in[0];
    const float* u      = (const float*)d_in[1];
    const float* gate_w = (const float*)d_in[2];
    const float* z_w1   = (const float*)d_in[3];
    const float* z_b1   = (const float*)d_in[4];
    const float* z_w2   = (const float*)d_in[5];
    const float* z_b2   = (const float*)d_in[6];
    const float* Umat   = (const float*)d_in[7];
    const float* Wg     = (const float*)d_in[8];
    const float* Wu     = (const float*)d_in[9];
    const float* Wd     = (const float*)d_in[10];
    float* out = (float*)d_out;

    cudaFuncSetAttribute(k_gateup, cudaFuncAttributeMaxDynamicSharedMemorySize, GU_SMEM);
    cudaFuncSetAttribute(k_down,   cudaFuncAttributeMaxDynamicSharedMemorySize, DN_SMEM);

    k_zero<<<(TT * HD + 255) / 256, 256>>>(out, x);
    k_zh<<<dim3(ZHD / 64, TT / 128), 256>>>(x, z_w1, z_b1);
    k_router<<<TT, 128>>>(x, u, gate_w, z_w2, z_b2, Umat);
    k_gateup<<<dim3(FF / 32, EE), 256, GU_SMEM>>>(Wg, Wu);
    k_down<<<dim3(HD / 64, EE), 256, DN_SMEM>>>(Wd, out);
}

// round 14
// speedup vs baseline: 1.2332x; 1.2332x over previous
#include <cuda_runtime.h>
#include <cuda_fp16.h>
#include <cstdint>
#include <math.h>

#define TT   512
#define HD   2048
#define EE   32
#define KTOP 4
#define FF   1024
#define NZ   16
#define ZHD  512

__device__ float  g_zh[TT * ZHD];
__device__ __half g_xh[TT * HD];
__device__ __half g_acth[(size_t)EE * TT * FF];
__device__ int    g_cnt[EE];
__device__ int    g_tok[EE * TT];
__device__ float  g_wgt[EE * TT];

__device__ __forceinline__ unsigned f2tf(float f) {
    unsigned u;
    asm("cvt.rna.tf32.f32 %0, %1;" : "=r"(u) : "f"(f));
    return u;
}
__device__ __forceinline__ unsigned pack_h2(float lo, float hi) {
    unsigned d;
    asm("cvt.rn.f16x2.f32 %0, %1, %2;" : "=r"(d) : "f"(hi), "f"(lo));
    return d;
}
__device__ __forceinline__ uint32_t smem_u32(const void* p) {
    uint32_t a;
    asm("{ .reg .u64 t; cvta.to.shared.u64 t, %1; cvt.u32.u64 %0, t; }" : "=r"(a) : "l"(p));
    return a;
}
__device__ __forceinline__ void cp16(uint32_t dst, const void* src) {
    asm volatile("cp.async.cg.shared.global [%0], [%1], 16;" :: "r"(dst), "l"(src));
}
#define CP_COMMIT() asm volatile("cp.async.commit_group;" ::: "memory")
#define CP_WAIT4()  asm volatile("cp.async.wait_group 4;" ::: "memory")

__device__ __forceinline__ void mma_tf32(float& d0, float& d1, float& d2, float& d3,
                                         unsigned a0, unsigned a1, unsigned a2, unsigned a3,
                                         unsigned b0, unsigned b1) {
    asm volatile("mma.sync.aligned.m16n8k8.row.col.f32.tf32.tf32.f32 "
                 "{%0,%1,%2,%3}, {%4,%5,%6,%7}, {%8,%9}, {%0,%1,%2,%3};"
                 : "+f"(d0), "+f"(d1), "+f"(d2), "+f"(d3)
                 : "r"(a0), "r"(a1), "r"(a2), "r"(a3), "r"(b0), "r"(b1));
}
__device__ __forceinline__ void mma_f16(float& d0, float& d1, float& d2, float& d3,
                                        unsigned a0, unsigned a1, unsigned a2, unsigned a3,
                                        unsigned b0, unsigned b1) {
    asm volatile("mma.sync.aligned.m16n8k16.row.col.f32.f16.f16.f32 "
                 "{%0,%1,%2,%3}, {%4,%5,%6,%7}, {%8,%9}, {%0,%1,%2,%3};"
                 : "+f"(d0), "+f"(d1), "+f"(d2), "+f"(d3)
                 : "r"(a0), "r"(a1), "r"(a2), "r"(a3), "r"(b0), "r"(b1));
}

// ---------------------------------------------------------------------------
// K0: zero output + counters + fp16 copy of x
// ---------------------------------------------------------------------------
__global__ void k_zero(float* __restrict__ out, const float* __restrict__ x) {
    int i = blockIdx.x * blockDim.x + threadIdx.x;
    if (i < TT * HD) {
        out[i] = 0.0f;
        g_xh[i] = __float2half_rn(x[i]);
    }
    if (i < EE) g_cnt[i] = 0;
}

// ---------------------------------------------------------------------------
// K1: zh = silu(x @ z_w1^T + b1). tf32 (small; unchanged)
// ---------------------------------------------------------------------------
__global__ __launch_bounds__(256, 2) void k_zh(const float* __restrict__ x,
                                               const float* __restrict__ w1,
                                               const float* __restrict__ b1) {
    int m0 = blockIdx.y * 128, n0 = blockIdx.x * 64;
    __shared__ unsigned As[128][20];
    __shared__ unsigned Bs[64][20];
    int tid = threadIdx.x, lane = tid & 31, warp = tid >> 5;
    int wm = warp >> 1, wn = warp & 1;
    int lq = lane >> 2, lr = lane & 3;
    int bn = tid >> 2, bkc = (tid & 3) * 4;

    float acc[2][4][4] = {};
    float4 rA[2], rB;
#pragma unroll
    for (int p = 0; p < 2; p++) {
        int s = tid + p * 256, r = s >> 2, kc = (s & 3) * 4;
        rA[p] = *(const float4*)&x[(size_t)(m0 + r) * HD + kc];
    }
    rB = *(const float4*)&w1[(size_t)(n0 + bn) * HD + bkc];
#pragma unroll
    for (int p = 0; p < 2; p++) {
        int s = tid + p * 256, r = s >> 2, kc = (s & 3) * 4;
        uint4 w = {f2tf(rA[p].x), f2tf(rA[p].y), f2tf(rA[p].z), f2tf(rA[p].w)};
        *(uint4*)&As[r][kc] = w;
    }
    {
        uint4 w = {f2tf(rB.x), f2tf(rB.y), f2tf(rB.z), f2tf(rB.w)};
        *(uint4*)&Bs[bn][bkc] = w;
    }
    __syncthreads();

    for (int k0 = 0; k0 < HD; k0 += 16) {
        bool more = (k0 + 16) < HD;
        if (more) {
            int kn = k0 + 16;
#pragma unroll
            for (int p = 0; p < 2; p++) {
                int s = tid + p * 256, r = s >> 2, kc = (s & 3) * 4;
                rA[p] = *(const float4*)&x[(size_t)(m0 + r) * HD + kn + kc];
            }
            rB = *(const float4*)&w1[(size_t)(n0 + bn) * HD + kn + bkc];
        }
#pragma unroll
        for (int k8 = 0; k8 < 2; k8++) {
            int kb = k8 * 8 + lr;
            unsigned a[2][4];
#pragma unroll
            for (int mi = 0; mi < 2; mi++) {
                int r = wm * 32 + mi * 16 + lq;
                a[mi][0] = As[r][kb];     a[mi][1] = As[r + 8][kb];
                a[mi][2] = As[r][kb + 4]; a[mi][3] = As[r + 8][kb + 4];
            }
#pragma unroll
            for (int ni = 0; ni < 4; ni++) {
                int nn = wn * 32 + ni * 8 + lq;
                unsigned b0 = Bs[nn][kb], b1r = Bs[nn][kb + 4];
#pragma unroll
                for (int mi = 0; mi < 2; mi++)
                    mma_tf32(acc[mi][ni][0], acc[mi][ni][1], acc[mi][ni][2], acc[mi][ni][3],
                             a[mi][0], a[mi][1], a[mi][2], a[mi][3], b0, b1r);
            }
        }
        __syncthreads();
        if (more) {
#pragma unroll
            for (int p = 0; p < 2; p++) {
                int s = tid + p * 256, r = s >> 2, kc = (s & 3) * 4;
                uint4 w = {f2tf(rA[p].x), f2tf(rA[p].y), f2tf(rA[p].z), f2tf(rA[p].w)};
                *(uint4*)&As[r][kc] = w;
            }
            uint4 w = {f2tf(rB.x), f2tf(rB.y), f2tf(rB.z), f2tf(rB.w)};
            *(uint4*)&Bs[bn][bkc] = w;
            __syncthreads();
        }
    }
#pragma unroll
    for (int mi = 0; mi < 2; mi++)
#pragma unroll
        for (int half = 0; half < 2; half++) {
            int r = m0 + wm * 32 + mi * 16 + lq + half * 8;
#pragma unroll
            for (int ni = 0; ni < 4; ni++)
#pragma unroll
                for (int c = 0; c < 2; c++) {
                    int col = n0 + wn * 32 + ni * 8 + lr * 2 + c;
                    float v = acc[mi][ni][half * 2 + c] + b1[col];
                    g_zh[(size_t)r * ZHD + col] = v / (1.0f + expf(-v));
                }
        }
}

// ---------------------------------------------------------------------------
// K2: per-token router (unchanged)
// ---------------------------------------------------------------------------
__global__ __launch_bounds__(128) void k_router(const float* __restrict__ x,
                                                const float* __restrict__ u,
                                                const float* __restrict__ gate_w,
                                                const float* __restrict__ z_w2,
                                                const float* __restrict__ z_b2,
                                                const float* __restrict__ Umat) {
    int t = blockIdx.x;
    __shared__ float xs[HD];
    __shared__ float rl[EE];
    __shared__ float zl[NZ];
    int tid = threadIdx.x, lane = tid & 31, warp = tid >> 5;

    for (int i = tid; i < HD; i += 128) xs[i] = x[t * HD + i];
    __syncthreads();

    for (int e = warp; e < EE; e += 4) {
        float s = 0.0f;
        const float* gw = gate_w + e * HD;
        for (int i = lane; i < HD; i += 32) s += xs[i] * gw[i];
#pragma unroll
        for (int o = 16; o; o >>= 1) s += __shfl_down_sync(0xffffffffu, s, o);
        if (lane == 0) rl[e] = s;
    }
    for (int j = warp; j < NZ; j += 4) {
        float s = 0.0f;
        const float* zw = z_w2 + j * ZHD;
        const float* zh = g_zh + t * ZHD;
        for (int i = lane; i < ZHD; i += 32) s += zh[i] * zw[i];
#pragma unroll
        for (int o = 16; o; o >>= 1) s += __shfl_down_sync(0xffffffffu, s, o);
        if (lane == 0) zl[j] = s + z_b2[j];
    }
    __syncthreads();

    if (tid == 0) {
        int zi = 0;
        float best = -1e30f;
        for (int j = 0; j < NZ; j++) {
            float g = -logf(-logf(u[t * NZ + j]));
            float v = zl[j] + g;
            if (v > best) { best = v; zi = j; }
        }
        float lg[EE];
        float mx = -1e30f;
        for (int e = 0; e < EE; e++) {
            lg[e] = rl[e] + Umat[zi * EE + e];
            mx = fmaxf(mx, lg[e]);
        }
        float sum = 0.0f;
        for (int e = 0; e < EE; e++) { lg[e] = expf(lg[e] - mx); sum += lg[e]; }
        float inv = 1.0f / sum;
        for (int k = 0; k < KTOP; k++) {
            int be = 0;
            float bv = -1.0f;
            for (int e = 0; e < EE; e++)
                if (lg[e] > bv) { bv = lg[e]; be = e; }
            float w = bv * inv;
            lg[be] = -1.0f;
            int pos = atomicAdd(&g_cnt[be], 1);
            g_tok[be * TT + pos] = t;
            g_wgt[be * TT + pos] = w;
        }
    }
}

// ---------------------------------------------------------------------------
// K3: gate/up, 6-stage cp.async, fp16 mma (R8 config — proven 208us).
// CTA: M=128 tokens x N=64 f-cols of both Wg and Wu. grid (FF/64, EE).
// Stage (14848 B): A fp16 [128][12w] (6144) | Bg f32 [16][68w] | Bu f32 [16][68w]
// ---------------------------------------------------------------------------
#define GU_ST    14848
#define GU_SMEM  (1024 + 6 * GU_ST)

__global__ __launch_bounds__(256) void k_gateup(const float* __restrict__ Wg,
                                                const float* __restrict__ Wu) {
    extern __shared__ char smem[];
    int e = blockIdx.y;
    int n = g_cnt[e];
    if (n == 0) return;
    int f0 = blockIdx.x * 64;
    uint32_t sb = smem_u32(smem);
    int tid = threadIdx.x, lane = tid & 31, warp = tid >> 5;
    int wm = warp >> 1, wn = warp & 1;
    int lq = lane >> 2, lr = lane & 3;
    int* toks = (int*)smem;
    const float* wg = Wg + (size_t)e * HD * FF + f0;
    const float* wu = Wu + (size_t)e * HD * FF + f0;

    int ar = tid >> 1, ac = tid & 1;
    int bkk = tid >> 4, bcc = tid & 15;

    for (int s0 = 0; s0 < n; s0 += 128) {
        __syncthreads();
        int nt = min(128, n - s0);
        if (tid < 128) toks[tid] = g_tok[e * TT + s0 + ((tid < nt) ? tid : 0)];
        __syncthreads();
        const __half* xrow = g_xh + (size_t)toks[ar] * HD;

#pragma unroll
        for (int s = 0; s < 5; s++) {
            uint32_t st = sb + 1024 + s * GU_ST;
            cp16(st + ar * 48 + ac * 16, xrow + s * 16 + ac * 8);
            cp16(st + 6144 + bkk * 272 + bcc * 16, wg + (size_t)(s * 16 + bkk) * FF + bcc * 4);
            cp16(st + 10496 + bkk * 272 + bcc * 16, wu + (size_t)(s * 16 + bkk) * FF + bcc * 4);
            CP_COMMIT();
        }

        float accg[2][4][4] = {}, accu[2][4][4] = {};

        int cur = 0;
        for (int i = 0; i < 128; i++) {
            CP_WAIT4();
            __syncthreads();
            int nx = i + 5;
            if (nx < 128) {
                int nst = nx % 6;
                uint32_t st = sb + 1024 + nst * GU_ST;
                int kn = nx * 16;
                cp16(st + ar * 48 + ac * 16, xrow + kn + ac * 8);
                cp16(st + 6144 + bkk * 272 + bcc * 16, wg + (size_t)(kn + bkk) * FF + bcc * 4);
                cp16(st + 10496 + bkk * 272 + bcc * 16, wu + (size_t)(kn + bkk) * FF + bcc * 4);
            }
            CP_COMMIT();

            const char* stg = smem + 1024 + cur * GU_ST;
            const unsigned* Aw = (const unsigned*)stg;
            const float* Bg = (const float*)(stg + 6144);
            const float* Bu = (const float*)(stg + 10496);

            unsigned a[2][4];
#pragma unroll
            for (int mi = 0; mi < 2; mi++) {
                int r = wm * 32 + mi * 16 + lq;
                a[mi][0] = Aw[r * 12 + lr];
                a[mi][1] = Aw[(r + 8) * 12 + lr];
                a[mi][2] = Aw[r * 12 + lr + 4];
                a[mi][3] = Aw[(r + 8) * 12 + lr + 4];
            }
#pragma unroll
            for (int ni = 0; ni < 4; ni++) {
                int nn = wn * 32 + ni * 8 + lq;
                unsigned g0 = pack_h2(Bg[(2 * lr) * 68 + nn],     Bg[(2 * lr + 1) * 68 + nn]);
                unsigned g1 = pack_h2(Bg[(2 * lr + 8) * 68 + nn], Bg[(2 * lr + 9) * 68 + nn]);
                unsigned u0 = pack_h2(Bu[(2 * lr) * 68 + nn],     Bu[(2 * lr + 1) * 68 + nn]);
                unsigned u1 = pack_h2(Bu[(2 * lr + 8) * 68 + nn], Bu[(2 * lr + 9) * 68 + nn]);
#pragma unroll
                for (int mi = 0; mi < 2; mi++) {
                    mma_f16(accg[mi][ni][0], accg[mi][ni][1], accg[mi][ni][2], accg[mi][ni][3],
                            a[mi][0], a[mi][1], a[mi][2], a[mi][3], g0, g1);
                    mma_f16(accu[mi][ni][0], accu[mi][ni][1], accu[mi][ni][2], accu[mi][ni][3],
                            a[mi][0], a[mi][1], a[mi][2], a[mi][3], u0, u1);
                }
            }
            if (++cur == 6) cur = 0;
        }

        // epilogue: SwiGLU * comb -> g_acth (fp16)
#pragma unroll
        for (int mi = 0; mi < 2; mi++)
#pragma unroll
            for (int half = 0; half < 2; half++) {
                int r = wm * 32 + mi * 16 + lq + half * 8;
                if (r < nt) {
                    float wc = g_wgt[e * TT + s0 + r];
                    size_t base = ((size_t)e * TT + s0 + r) * FF + f0 + wn * 32;
#pragma unroll
                    for (int ni = 0; ni < 4; ni++) {
                        float av[2];
#pragma unroll
                        for (int c = 0; c < 2; c++) {
                            float gv = accg[mi][ni][half * 2 + c];
                            float uv = accu[mi][ni][half * 2 + c];
                            av[c] = gv / (1.0f + expf(-gv)) * uv * wc;
                        }
                        *(unsigned*)&g_acth[base + ni * 8 + lr * 2] = pack_h2(av[0], av[1]);
                    }
                }
            }
    }
}

// ---------------------------------------------------------------------------
// K4: down projection, M=64 x N=128, K=FF, fp16 mma, 3 CTAs/SM, 6-stage.
// grid (HD/128, EE) = 512. 8 warps: wm {0,1} x wn {0..3}, warp m32 x n32.
// Stage (11520 B): A fp16 [64][12w] (3072) | B f32 [16][132w] (8448)
// ---------------------------------------------------------------------------
#define DN_ST    11520
#define DN_SMEM  (1024 + 6 * DN_ST)

__global__ __launch_bounds__(256, 3) void k_down(const float* __restrict__ Wd,
                                                 float* __restrict__ out) {
    extern __shared__ char smem[];
    int e = blockIdx.y;
    int n = g_cnt[e];
    if (n == 0) return;
    int h0 = blockIdx.x * 128;
    uint32_t sb = smem_u32(smem);
    int tid = threadIdx.x, lane = tid & 31, warp = tid >> 5;
    int wm = warp >> 2, wn = warp & 3;
    int lq = lane >> 2, lr = lane & 3;
    int* toks = (int*)smem;
    const float* wd = Wd + (size_t)e * FF * HD + h0;

    int arow_i = tid >> 1, ach = tid & 1;   // A staging (tid < 128)

    for (int s0 = 0; s0 < n; s0 += 64) {
        __syncthreads();
        int nt = min(64, n - s0);
        if (tid < 64) toks[tid] = g_tok[e * TT + s0 + ((tid < nt) ? tid : 0)];
        __syncthreads();

        const __half* arow = g_acth +
            ((size_t)e * TT + s0 + ((arow_i < nt) ? arow_i : 0)) * FF;

#pragma unroll
        for (int s = 0; s < 5; s++) {
            uint32_t st = sb + 1024 + s * DN_ST;
            if (tid < 128)
                cp16(st + arow_i * 48 + ach * 16, arow + s * 16 + ach * 8);
#pragma unroll
            for (int p = 0; p < 2; p++) {
                int c = tid + p * 256;
                int row = c >> 5, col = c & 31;
                cp16(st + 3072 + row * 528 + col * 16,
                     wd + (size_t)(s * 16 + row) * HD + col * 4);
            }
            CP_COMMIT();
        }

        float acc[2][4][4] = {};

        int cur = 0;
        for (int i = 0; i < 64; i++) {
            CP_WAIT4();
            __syncthreads();
            int nx = i + 5;
            if (nx < 64) {
                int nst = nx % 6;
                uint32_t st = sb + 1024 + nst * DN_ST;
                int kn = nx * 16;
                if (tid < 128)
                    cp16(st + arow_i * 48 + ach * 16, arow + kn + ach * 8);
#pragma unroll
                for (int p = 0; p < 2; p++) {
                    int c = tid + p * 256;
                    int row = c >> 5, col = c & 31;
                    cp16(st + 3072 + row * 528 + col * 16,
                         wd + (size_t)(kn + row) * HD + col * 4);
                }
            }
            CP_COMMIT();

            const char* stg = smem + 1024 + cur * DN_ST;
            const unsigned* Aw = (const unsigned*)stg;
            const float* B = (const float*)(stg + 3072);

            unsigned a[2][4];
#pragma unroll
            for (int mi = 0; mi < 2; mi++) {
                int r = wm * 32 + mi * 16 + lq;
                a[mi][0] = Aw[r * 12 + lr];
                a[mi][1] = Aw[(r + 8) * 12 + lr];
                a[mi][2] = Aw[r * 12 + lr + 4];
                a[mi][3] = Aw[(r + 8) * 12 + lr + 4];
            }
#pragma unroll
            for (int ni = 0; ni < 4; ni++) {
                int nn = wn * 32 + ni * 8 + lq;
                unsigned b0 = pack_h2(B[(2 * lr) * 132 + nn],     B[(2 * lr + 1) * 132 + nn]);
                unsigned b1 = pack_h2(B[(2 * lr + 8) * 132 + nn], B[(2 * lr + 9) * 132 + nn]);
#pragma unroll
                for (int mi = 0; mi < 2; mi++)
                    mma_f16(acc[mi][ni][0], acc[mi][ni][1], acc[mi][ni][2], acc[mi][ni][3],
                            a[mi][0], a[mi][1], a[mi][2], a[mi][3], b0, b1);
            }
            if (++cur == 6) cur = 0;
        }

        // epilogue: atomicAdd into out
#pragma unroll
        for (int mi = 0; mi < 2; mi++)
#pragma unroll
            for (int half = 0; half < 2; half++) {
                int r = wm * 32 + mi * 16 + lq + half * 8;
                if (r < nt) {
                    int t = toks[r];
                    size_t base = (size_t)t * HD + h0 + wn * 32;
#pragma unroll
                    for (int ni = 0; ni < 4; ni++)
#pragma unroll
                        for (int c = 0; c < 2; c++)
                            atomicAdd(&out[base + ni * 8 + lr * 2 + c],
                                      acc[mi][ni][half * 2 + c]);
                }
            }
    }
}

// ---------------------------------------------------------------------------
// launch
// ---------------------------------------------------------------------------
extern "C" void kernel_launch(void* const* d_in, const int* in_sizes, int n_in,
                              void* d_out, int out_size) {
    const float* x      = (const float*)d_in[0];
    const float* u      = (const float*)d_in[1];
    const float* gate_w = (const float*)d_in[2];
    const float* z_w1   = (const float*)d_in[3];
    const float* z_b1   = (const float*)d_in[4];
    const float* z_w2   = (const float*)d_in[5];
    const float* z_b2   = (const float*)d_in[6];
    const float* Umat   = (const float*)d_in[7];
    const float* Wg     = (const float*)d_in[8];
    const float* Wu     = (const float*)d_in[9];
    const float* Wd     = (const float*)d_in[10];
    float* out = (float*)d_out;

    cudaFuncSetAttribute(k_gateup, cudaFuncAttributeMaxDynamicSharedMemorySize, GU_SMEM);
    cudaFuncSetAttribute(k_down,   cudaFuncAttributeMaxDynamicSharedMemorySize, DN_SMEM);

    k_zero<<<(TT * HD + 255) / 256, 256>>>(out, x);
    k_zh<<<dim3(ZHD / 64, TT / 128), 256>>>(x, z_w1, z_b1);
    k_router<<<TT, 128>>>(x, u, gate_w, z_w2, z_b2, Umat);
    k_gateup<<<dim3(FF / 64, EE), 256, GU_SMEM>>>(Wg, Wu);
    k_down<<<dim3(HD / 128, EE), 256, DN_SMEM>>>(Wd, out);
}